// round 2
// baseline (speedup 1.0000x reference)
#include <cuda_runtime.h>
#include <math.h>

#define SAC_WARMUP 365
#define PF 4

__device__ __forceinline__ float fast_lg2(float x) {
    float r;
    asm("lg2.approx.f32 %0, %1;" : "=f"(r) : "f"(x));
    return r;
}
__device__ __forceinline__ float fast_ex2(float x) {
    float r;
    asm("ex2.approx.f32 %0, %1;" : "=f"(r) : "f"(x));
    return r;
}

__global__ __launch_bounds__(32)
void sac4dpl_kernel(const float* __restrict__ p_and_e,   // [T, B, 2]
                    const float* __restrict__ params,    // [B, 21]
                    float* __restrict__ out,             // [2, T-WARMUP, B]
                    int T, int B)
{
    int b = blockIdx.x * 32 + threadIdx.x;
    if (b >= B) return;

    // ---- load + scale parameters (one-time) ----
    const float lo[21] = {0.1f, 0.0f, 0.0f, 10.0f, 10.0f, 50.0f, 10.0f, 50.0f,
                          0.0f, 0.0f, 0.0f, 5.0f, 1.0f, 0.1f, 0.01f, 0.001f,
                          0.5f, 0.95f, 0.98f, 0.0f, 0.0f};
    const float hi[21] = {1.2f, 0.1f, 0.3f, 100.0f, 100.0f, 400.0f, 100.0f, 1000.0f,
                          0.3f, 0.5f, 0.1f, 350.0f, 4.0f, 0.5f, 0.35f, 0.05f,
                          0.9f, 0.998f, 0.998f, 1.0f, 0.5f};
    float pr[21];
#pragma unroll
    for (int i = 0; i < 21; i++)
        pr[i] = lo[i] + params[(size_t)b * 21 + i] * (hi[i] - lo[i]);

    const float kc    = pr[0],  pctim = pr[1],  adimp = pr[2];
    const float uztwm = pr[3],  uzfwm = pr[4],  lztwm = pr[5];
    const float lzfsm = pr[6],  lzfpm = pr[7];
    const float pfree = pr[9],  riva  = pr[10];
    const float zperc = pr[11], rexp  = pr[12], uzk = pr[13];
    const float lzsk  = pr[14], lzpk  = pr[15];
    const float ci    = pr[16], cgs   = pr[17], cgp = pr[18];
    const float ke    = pr[19], xe    = pr[20];

    // ---- precomputed per-basin constants (hoist all static divisions) ----
    const float r_uztwm = 1.0f / uztwm;
    const float r_lztwm = 1.0f / lztwm;
    const float r_ulz   = 1.0f / (uztwm + lztwm);
    const float r_lzfsm = 1.0f / lzfsm;
    const float r_lzfpm = 1.0f / lzfpm;
    const float sfm     = lzfsm + lzfpm;            // LZFSM + LZFPM
    const float lzsum   = sfm + lztwm;              // LZFSM + LZFPM + LZTWM
    const float r_lzsum = 1.0f / lzsum;
    const float uzsum   = uztwm + uzfwm;
    const float pbase   = lzfsm * lzsk + lzfpm * lzpk;
    const float parea   = 1.0f - pctim - adimp;
    const float fp_frac = lzfpm / sfm;
    const float pbu     = pbase / uzfwm;            // pbase / uzfwm
    const float pbuz    = pbu * zperc;              // pbase*zperc/uzfwm
    const float ci1     = (1.0f - ci)  * parea;
    const float cgs1    = (1.0f - cgs) * parea;
    const float cgp1    = (1.0f - cgp) * parea;
    const float dt      = 0.5f;
    const float mden    = ke * (1.0f - xe) + dt;
    const float c1      = (ke * xe + dt) / mden;
    const float c2      = (dt - ke * xe) / mden;
    const float c3      = (ke * (1.0f - xe) - dt) / mden;

    // ---- initial carry ----
    float auztw = 0.01f, alztw = 0.01f;
    float uztw  = 0.01f, uzfw  = 0.01f;
    float lztw  = 0.01f, lzfs  = 0.01f, lzfp = 0.01f;
    float qs = 0.01f, qi = 0.01f, qgs = 0.01f, qgp = 0.01f;
    float o1 = 0.01f;

    const float2* __restrict__ pe2 = (const float2*)p_and_e;
    const int nout = T - SAC_WARMUP;
    float* __restrict__ qout = out;
    float* __restrict__ eout = out + (size_t)nout * B;

    // ---- 4-deep prefetch ring (hides ~577cy DRAM latency behind 4 steps of compute) ----
    float2 buf[PF];
#pragma unroll
    for (int i = 0; i < PF; i++)
        buf[i] = pe2[(size_t)i * B + b];

#pragma unroll 4
    for (int t = 0; t < T; ++t) {
        float2 cur = buf[t & (PF - 1)];
        int tp = t + PF;
        if (tp < T)
            buf[t & (PF - 1)] = pe2[(size_t)tp * B + b];

        float p = fmaxf(cur.x, 0.0f);
        float e = cur.y;
        if (!isfinite(e)) e = 0.0f;
        e = fmaxf(e, 0.0f);

        float ep    = kc * e;
        float roimp = pctim * p;
        float ae2   = pctim * ep;

        // ADIMP (additional impervious) water balance
        float ae1    = fminf(auztw, ep * (auztw * r_uztwm));
        float ae3    = fmaxf((ep - ae1) * (alztw * r_ulz), 0.0f);
        float pav    = fmaxf(p - (uztwm - (auztw - ae1)), 0.0f);
        float almae3 = alztw - ae3;
        float adsur  = fmaxf(pav * (almae3 * r_lztwm), 0.0f);
        float ars    = fmaxf(pav - adsur + almae3 - lztwm, 0.0f);
        float auztw_n = fmaxf(fminf(uztwm, auztw - ae1 + p), 0.0f);
        float alztw_n = fmaxf(fminf(lztwm, pav - adsur + almae3), 0.0f);

        // pervious-area ET
        float e1  = fminf(uztw, ep * (uztw * r_uztwm));
        float e2  = fmaxf(fminf(uzfw, ep - e1), 0.0f);
        float e3  = fmaxf((ep - e1 - e2) * (lztw * r_ulz), 0.0f);
        float lt1 = fmaxf(lztw - e3, 0.0f);
        float e4  = riva * ep;
        float et  = ae2 + ae1 + ae3 + e1 + e2 + e3 + e4;

        // upper-zone water balance
        float uzres = p + (uztw + uzfw - e1 - e2);
        float rs = fmaxf(uzres - uzsum, 0.0f) * parea;
        float ut = fmaxf(fminf(uztwm, uztw - e1 + p), 0.0f);
        float uf = fmaxf(fminf(uzfwm, uzres - ut), 0.0f);
        float ri = uf * uzk;
        uf = fmaxf(uf - ri, 0.0f);

        // percolation (coef depends only on carry -> off critical path)
        float coef = fp_frac * (2.0f * (1.0f - lzfp * r_lzfpm))
                   / ((1.0f - lzfp * r_lzfpm) + (1.0f - lzfs * r_lzfsm));
        coef = fminf(coef, 1.0f);

        float lzdef = lzfs + lzfp + lt1;
        float defr  = fmaxf(1.0f - lzdef * r_lzsum, 0.0f);
        float pw    = fast_ex2(rexp * fast_lg2(defr));   // defr^rexp; lg2(0)=-inf -> ex2(-inf)=0
        float perc  = (pbu + pbuz * pw) * uf;
        float rate  = fmaxf(fminf(perc, lzsum - lzdef), 0.0f);
        uf = fmaxf(uf - rate, 0.0f);

        float fx    = fmaxf(fminf(sfm - (lzfs + lzfp),
                                  fmaxf(rate - (lztwm - lt1), rate * pfree)), 0.0f);
        float perct = rate - fx;
        float percp = fmaxf(fminf(lzfpm - lzfp,
                                  fmaxf(fx - (lzfsm - lzfs), coef * fx)), 0.0f);
        float percs = fmaxf(fx - percp, 0.0f);

        float lt = fminf(lt1 + perct, lztwm);
        float ls = lzfs + percs;
        float lp = lzfp + percp;
        float rgs = ls * lzsk;  ls = fmaxf(ls - rgs, 0.0f);
        float rgp = lp * lzpk;  lp = fmaxf(lp - rgp, 0.0f);

        // routing
        float i1   = qs + qi + qgs + qgp;
        float qs_n = roimp + adsur * adimp + ars * adimp + rs;
        float qi_n = ci  * qi  + ci1  * ri;
        float qgs_n = cgs * qgs + cgs1 * rgs;
        float qgp_n = cgp * qgp + cgp1 * rgp;
        float i2   = qs_n + qi_n + qgs_n + qgp_n;
        float o2   = c1 * i1 + c2 * i2 + c3 * o1;

        if (t >= SAC_WARMUP) {
            size_t o = (size_t)(t - SAC_WARMUP) * B + b;
            qout[o] = o2;
            eout[o] = et;
        }

        // commit carry
        auztw = auztw_n; alztw = alztw_n;
        uztw = ut; uzfw = uf; lztw = lt; lzfs = ls; lzfp = lp;
        qs = qs_n; qi = qi_n; qgs = qgs_n; qgp = qgp_n;
        o1 = o2;
    }
}

extern "C" void kernel_launch(void* const* d_in, const int* in_sizes, int n_in,
                              void* d_out, int out_size)
{
    const float* p_and_e = (const float*)d_in[0];   // [T, B, 2]
    const float* params  = (const float*)d_in[1];   // [B, 21]
    float* out = (float*)d_out;

    int B = in_sizes[1] / 21;
    int T = in_sizes[0] / (2 * B);

    int grid = (B + 31) / 32;
    sac4dpl_kernel<<<grid, 32>>>(p_and_e, params, out, T, B);
}